// round 7
// baseline (speedup 1.0000x reference)
#include <cuda_runtime.h>
#include <math.h>

#define K_SEL 30
#define K_NRM 8
#define NWARPS 8
#define QPW 2                     // queries per warp
#define TILE 2048
#define FULL 0xFFFFFFFFu

// 7x7 quadratic-form matrix S (includes 1/sqrt(128) scale), computed by prep kernel.
__device__ float g_S[49];

// ---------------------------------------------------------------------------
// Prep: S = (G Wq^T [+bq on homog row]) (G Wk^T [+bk])^T / sqrt(128)
// G[j][c] = fc_w[c][j] (j<6), G[6][c] = fc_b[c].
// scores[k,l] = y_k . S . y_l  with y = [pos_rel, normal_rel, 1]  (exact collapse
// of the fc -> Wq/Wk -> QK^T pipeline, since everything is affine in y).
// ---------------------------------------------------------------------------
__global__ void prep_kernel(const float* __restrict__ fc_w, const float* __restrict__ fc_b,
                            const float* __restrict__ wq_w, const float* __restrict__ wq_b,
                            const float* __restrict__ wk_w, const float* __restrict__ wk_b) {
    __shared__ float sG[7][128];
    __shared__ float sHq[7][128];
    __shared__ float sHk[7][128];
    int t = threadIdx.x; // 128 threads
    #pragma unroll
    for (int j = 0; j < 6; ++j) sG[j][t] = fc_w[t * 6 + j];
    sG[6][t] = fc_b[t];
    __syncthreads();

    float aq[7] = {0,0,0,0,0,0,0};
    float ak[7] = {0,0,0,0,0,0,0};
    for (int c = 0; c < 128; ++c) {
        float wq = wq_w[t * 128 + c];
        float wk = wk_w[t * 128 + c];
        #pragma unroll
        for (int j = 0; j < 7; ++j) {
            aq[j] += sG[j][c] * wq;
            ak[j] += sG[j][c] * wk;
        }
    }
    aq[6] += wq_b[t];
    ak[6] += wk_b[t];
    #pragma unroll
    for (int j = 0; j < 7; ++j) { sHq[j][t] = aq[j]; sHk[j][t] = ak[j]; }
    __syncthreads();

    if (t < 49) {
        int i = t / 7, j = t % 7;
        float s = 0.f;
        for (int d = 0; d < 128; ++d) s += sHq[i][d] * sHk[j][d];
        g_S[t] = s * (1.0f / 11.313708498984760390f); // 1/sqrt(128)
    }
}

// Warp-collective slow path: insert the candidates flagged in `mask` into the
// warp-distributed sorted top-32 list `key` (lane i = rank i, 64-bit key =
// dist_bits<<32 | idx, exact lax.top_k tie-break). Handles mask==0 as no-op.
// thr_d is refreshed to lane-31's distance (warp-uniform).
__device__ __forceinline__ void topk_insert_masked(unsigned long long& key, float& thr_d,
                                                   unsigned mask, float d, unsigned idxval,
                                                   int lane) {
    if (mask) {                                        // warp-uniform
        const unsigned long long ck =
            ((unsigned long long)__float_as_uint(d) << 32) | idxval;
        unsigned long long thr = __shfl_sync(FULL, key, 31);
        do {
            const int src = __ffs(mask) - 1;
            mask &= mask - 1;
            const unsigned long long ins = __shfl_sync(FULL, ck, src);
            if (ins < thr) {   // exact (dist, idx) order, warp-uniform
                const unsigned lower = __ballot_sync(FULL, key < ins);
                const int pos = __popc(lower);
                const unsigned long long up = __shfl_up_sync(FULL, key, 1);
                if (lane > pos)       key = up;
                else if (lane == pos) key = ins;
                thr = __shfl_sync(FULL, key, 31);
            }
        } while (mask);
        thr_d = __uint_as_float((unsigned)(thr >> 32));
    }
}

// ---------------------------------------------------------------------------
// Main: 2 queries per warp, exact 30-NN each. One smem tile read serves both
// queries (halves LDS crossbar per query). Hot path has a single merged
// branch for both lists' insert tests. Then collapsed 7-dim attention
// epilogue, run sequentially for each of the warp's queries.
// ---------------------------------------------------------------------------
__global__ void __launch_bounds__(NWARPS * 32)
knn_attn_kernel(const float* __restrict__ x_world,
                const float* __restrict__ voxel_point,
                const float* __restrict__ voxel_normal,
                const float* __restrict__ v,
                float* __restrict__ out,
                int N, int M) {
    __shared__ union {
        float pts[TILE * 3];                   // streaming phase: xyz-packed tile
        struct {                               // epilogue phase (after barrier)
            float z[NWARPS][K_SEL][7];
            float v[NWARPS][K_SEL];
        } epi;
    } sm;
    __shared__ float sS[49];

    const int tid  = threadIdx.x;
    const int warp = tid >> 5;
    const int lane = tid & 31;

    if (tid < 49) sS[tid] = g_S[tid];

    const int q0 = (blockIdx.x * NWARPS + warp) * QPW;
    const bool v0 = (q0     < N);   // warp-uniform, loop-invariant
    const bool v1 = (q0 + 1 < N);
    float qx0 = 0.f, qy0 = 0.f, qz0 = 0.f;
    float qx1 = 0.f, qy1 = 0.f, qz1 = 0.f;
    if (v0) { qx0 = x_world[q0 * 3];     qy0 = x_world[q0 * 3 + 1];     qz0 = x_world[q0 * 3 + 2]; }
    if (v1) { qx1 = x_world[q0 * 3 + 3]; qy1 = x_world[q0 * 3 + 4];     qz1 = x_world[q0 * 3 + 5]; }

    unsigned long long key0 = ((unsigned long long)0x7F800000u << 32) | 0xFFFFFFFFu;
    unsigned long long key1 = key0;
    float thr0 = __int_as_float(0x7F800000);
    float thr1 = thr0;

    const int ntiles = (M + TILE - 1) / TILE;
    for (int t = 0; t < ntiles; ++t) {
        const int base = t * TILE;
        __syncthreads();   // protect previous tile's readers
        if (base + TILE <= M) {
            // fast path: straight vectorized copy (TILE*3 floats, 16B aligned)
            const float4* src = (const float4*)(voxel_point + base * 3);
            float4* dst = (float4*)sm.pts;
            #pragma unroll
            for (int i = tid; i < TILE * 3 / 4; i += NWARPS * 32) dst[i] = src[i];
        } else {
            for (int i = tid; i < TILE * 3; i += NWARPS * 32) {
                int g = base * 3 + i;
                sm.pts[i] = (g < M * 3) ? voxel_point[g] : __int_as_float(0x7F800000);
            }
        }
        __syncthreads();

        if (v1) {
            // hot path: both queries valid (always, for N multiple of QPW*NWARPS)
            #pragma unroll 8
            for (int j = 0; j < TILE / 32; ++j) {
                const int ci = j * 32 + lane;
                // 3x LDS.32, bank-conflict-free (stride 3 words, gcd(3,32)=1)
                const float px = sm.pts[ci * 3];
                const float py = sm.pts[ci * 3 + 1];
                const float pz = sm.pts[ci * 3 + 2];
                const unsigned gidx = (unsigned)(base + ci);

                const float dx0 = qx0 - px, dy0 = qy0 - py, dz0 = qz0 - pz;
                const float dx1 = qx1 - px, dy1 = qy1 - py, dz1 = qz1 - pz;
                const float d0 = fmaf(dx0, dx0, fmaf(dy0, dy0, dz0 * dz0));
                const float d1 = fmaf(dx1, dx1, fmaf(dy1, dy1, dz1 * dz1));

                // two ballots, one merged branch (conservative superset tests)
                const unsigned m0 = __ballot_sync(FULL, d0 <= thr0);
                const unsigned m1 = __ballot_sync(FULL, d1 <= thr1);
                if (m0 | m1) {   // warp-uniform, rare (~1-2% of batches)
                    topk_insert_masked(key0, thr0, m0, d0, gidx, lane);
                    topk_insert_masked(key1, thr1, m1, d1, gidx, lane);
                }
            }
        } else if (v0) {
            #pragma unroll 8
            for (int j = 0; j < TILE / 32; ++j) {
                const int ci = j * 32 + lane;
                const float px = sm.pts[ci * 3];
                const float py = sm.pts[ci * 3 + 1];
                const float pz = sm.pts[ci * 3 + 2];
                const float dx0 = qx0 - px, dy0 = qy0 - py, dz0 = qz0 - pz;
                const float d0 = fmaf(dx0, dx0, fmaf(dy0, dy0, dz0 * dz0));
                const unsigned m0 = __ballot_sync(FULL, d0 <= thr0);
                topk_insert_masked(key0, thr0, m0, d0, (unsigned)(base + ci), lane);
            }
        }
    }

    // barrier before overlaying epilogue scratch on the tile buffer
    __syncthreads();

    // ---------------- epilogue: collapsed attention, per query --------------
    #pragma unroll
    for (int qi = 0; qi < QPW; ++qi) {
        const int q = q0 + qi;
        if (q >= N) break;   // warp-uniform
        const unsigned long long key = qi ? key1 : key0;
        const float qx = qi ? qx1 : qx0;
        const float qy = qi ? qy1 : qy0;
        const float qz = qi ? qz1 : qz0;

        const unsigned idx = (unsigned)(key & 0xFFFFFFFFull);
        const bool act = (lane < K_SEL);

        float vnx = 0.f, vny = 0.f, vnz = 0.f;
        if (act) {
            vnx = voxel_normal[idx * 3];
            vny = voxel_normal[idx * 3 + 1];
            vnz = voxel_normal[idx * 3 + 2];
        }
        // x_normal = mean of 8 nearest normals
        float sx = (lane < K_NRM) ? vnx : 0.f;
        float sy = (lane < K_NRM) ? vny : 0.f;
        float sz = (lane < K_NRM) ? vnz : 0.f;
        #pragma unroll
        for (int o = 16; o > 0; o >>= 1) {
            sx += __shfl_xor_sync(FULL, sx, o);
            sy += __shfl_xor_sync(FULL, sy, o);
            sz += __shfl_xor_sync(FULL, sz, o);
        }
        sx *= 0.125f; sy *= 0.125f; sz *= 0.125f;

        float y[7];
        if (act) {
            const float px = voxel_point[idx * 3];
            const float py = voxel_point[idx * 3 + 1];
            const float pz = voxel_point[idx * 3 + 2];
            y[0] = qx - px; y[1] = qy - py; y[2] = qz - pz;
            y[3] = sx - vnx; y[4] = sy - vny; y[5] = sz - vnz;
            y[6] = 1.f;
            #pragma unroll
            for (int i = 0; i < 7; ++i) {
                float acc = 0.f;
                #pragma unroll
                for (int jj = 0; jj < 7; ++jj) acc += sS[i * 7 + jj] * y[jj];
                sm.epi.z[warp][lane][i] = acc;   // z_l = S y_l
            }
            sm.epi.v[warp][lane] = v[idx];
        }
        __syncwarp(FULL);

        float outk = 0.f;
        if (act) {
            // online softmax over l: score[k][l] = y_k . z_l
            float m = __int_as_float(0xFF800000); // -inf
            float se = 0.f, sv = 0.f;
            for (int l = 0; l < K_SEL; ++l) {
                float s = 0.f;
                #pragma unroll
                for (int i = 0; i < 7; ++i) s += y[i] * sm.epi.z[warp][l][i];
                const float mn = fmaxf(m, s);
                const float corr = __expf(m - mn);
                const float e = __expf(s - mn);
                se = se * corr + e;
                sv = sv * corr + e * sm.epi.v[warp][l];
                m = mn;
            }
            outk = sv / se;
        }
        float tot = act ? outk : 0.f;
        #pragma unroll
        for (int o = 16; o > 0; o >>= 1) tot += __shfl_xor_sync(FULL, tot, o);
        if (lane == 0) out[q] = tot * (1.0f / 30.0f);
        __syncwarp(FULL);   // epi scratch reused by next qi
    }
}

// ---------------------------------------------------------------------------
extern "C" void kernel_launch(void* const* d_in, const int* in_sizes, int n_in,
                              void* d_out, int out_size) {
    const float* x_world      = (const float*)d_in[0];
    const float* voxel_point  = (const float*)d_in[1];
    const float* voxel_normal = (const float*)d_in[2];
    const float* v            = (const float*)d_in[3];
    const float* fc_w         = (const float*)d_in[4];
    const float* fc_b         = (const float*)d_in[5];
    const float* wq_w         = (const float*)d_in[6];
    const float* wq_b         = (const float*)d_in[7];
    const float* wk_w         = (const float*)d_in[8];
    const float* wk_b         = (const float*)d_in[9];
    float* out = (float*)d_out;

    const int N = in_sizes[0] / 3;
    const int M = in_sizes[1] / 3;

    prep_kernel<<<1, 128>>>(fc_w, fc_b, wq_w, wq_b, wk_w, wk_b);

    const int qpb = NWARPS * QPW;
    const int blocks = (N + qpb - 1) / qpb;
    knn_attn_kernel<<<blocks, NWARPS * 32>>>(x_world, voxel_point, voxel_normal, v,
                                             out, N, M);
}